// round 15
// baseline (speedup 1.0000x reference)
#include <cuda_runtime.h>
#include <cuda_fp16.h>
#include <cstdint>

// Problem constants
#define Bb   4
#define Tt   2048
#define Cc   512
#define Hh   8
#define Dd   64
#define CDRH 2

#define NEG_INF  __int_as_float(0xff800000)
#define M_INIT   -1.0e30f
#define SCALE2 0.18033688011112042f   // 0.125 * log2(e)
#define ONES_H2 0x3C003C00u           // half2(1.0, 1.0)

// Scratch (allocation-free: module-static device globals)
__device__ __half g_xh[Bb * Tt * Cc];
__device__ __half g_wh[4][Cc * Cc];    // Wq, Wk, Wv, Wo in half
__device__ __half g_qh[Bb * Tt * Cc];
__device__ __half g_kh[Bb * Tt * Cc];
__device__ __half g_vh[Bb * Tt * Cc];
__device__ __half g_ctxh[Bb * Tt * Cc];
__device__ int    g_allm[Bb];

// ---------------------------------------------------------------------------
// helpers
// ---------------------------------------------------------------------------
__device__ __forceinline__ void mma_f16(float c[4], const uint32_t a[4],
                                        uint32_t b0, uint32_t b1) {
    asm volatile(
        "mma.sync.aligned.m16n8k16.row.col.f32.f16.f16.f32 "
        "{%0,%1,%2,%3}, {%4,%5,%6,%7}, {%8,%9}, {%0,%1,%2,%3};"
        : "+f"(c[0]), "+f"(c[1]), "+f"(c[2]), "+f"(c[3])
        : "r"(a[0]), "r"(a[1]), "r"(a[2]), "r"(a[3]), "r"(b0), "r"(b1));
}

__device__ __forceinline__ void ldsm_x4(uint32_t r[4], uint32_t addr) {
    asm volatile("ldmatrix.sync.aligned.m8n8.x4.shared.b16 {%0,%1,%2,%3}, [%4];"
                 : "=r"(r[0]), "=r"(r[1]), "=r"(r[2]), "=r"(r[3]) : "r"(addr));
}

__device__ __forceinline__ void ldsm_x4_t(uint32_t r[4], uint32_t addr) {
    asm volatile("ldmatrix.sync.aligned.m8n8.x4.trans.shared.b16 {%0,%1,%2,%3}, [%4];"
                 : "=r"(r[0]), "=r"(r[1]), "=r"(r[2]), "=r"(r[3]) : "r"(addr));
}

__device__ __forceinline__ uint32_t h2u(__half2 h) {
    return *reinterpret_cast<uint32_t*>(&h);
}

__device__ __forceinline__ float ex2(float x) {
    float y;
    asm("ex2.approx.f32 %0, %1;" : "=f"(y) : "f"(x));
    return y;
}

__device__ __forceinline__ uint32_t ex2h2(uint32_t x) {
    uint32_t y;
    asm("ex2.approx.f16x2 %0, %1;" : "=r"(y) : "r"(x));
    return y;
}

__device__ __forceinline__ void cp16(uint32_t dst, const void* src) {
    asm volatile("cp.async.cg.shared.global [%0], [%1], 16;" :: "r"(dst), "l"(src));
}
__device__ __forceinline__ void cp_commit() {
    asm volatile("cp.async.commit_group;");
}
template <int N>
__device__ __forceinline__ void cp_wait() {
    asm volatile("cp.async.wait_group %0;" :: "n"(N));
}

// ---------------------------------------------------------------------------
// Fused prep: fp32->half for x + 4 weights (grid.y 0..4), allm flag (y==5)
// ---------------------------------------------------------------------------
__global__ void prep_kernel(const float* __restrict__ x,
                            const float* __restrict__ Wq,
                            const float* __restrict__ Wk,
                            const float* __restrict__ Wv,
                            const float* __restrict__ Wo,
                            const int* __restrict__ cdrs) {
    const int y = blockIdx.y;
    if (y == 5) {
        int b = blockIdx.x;
        if (b >= Bb) return;
        __shared__ int any;
        if (threadIdx.x == 0) any = 0;
        __syncthreads();
        int local = 0;
        for (int t = threadIdx.x; t < Tt; t += blockDim.x)
            local |= (cdrs[b * Tt + t] != 0);
        if (local) any = 1;
        __syncthreads();
        if (threadIdx.x == 0) g_allm[b] = (any == 0) ? 1 : 0;
        return;
    }
    const float* src; __half* dst; int n4;
    switch (y) {
        case 0: src = x;  dst = g_xh;    n4 = Bb * Tt * Cc / 4; break;
        case 1: src = Wq; dst = g_wh[0]; n4 = Cc * Cc / 4; break;
        case 2: src = Wk; dst = g_wh[1]; n4 = Cc * Cc / 4; break;
        case 3: src = Wv; dst = g_wh[2]; n4 = Cc * Cc / 4; break;
        default: src = Wo; dst = g_wh[3]; n4 = Cc * Cc / 4; break;
    }
    int i = blockIdx.x * blockDim.x + threadIdx.x;
    if (i < n4) {
        float4 v = ((const float4*)src)[i];
        uint2 w;
        w.x = h2u(__floats2half2_rn(v.x, v.y));
        w.y = h2u(__floats2half2_rn(v.z, v.w));
        ((uint2*)dst)[i] = w;
    }
}

// ---------------------------------------------------------------------------
// fp16 tensor-core GEMM (round-12 shape), BK=32, 3-stage cp.async.
// 8 warps (2m x 4n); warp tile 64x32 via m16n8k16 + LDSM.
// ---------------------------------------------------------------------------
#define APIT 40    // As pitch in halves (80 B)
#define BPIT 136   // Bs pitch in halves (272 B)
#define AS_BYTES (128 * APIT * 2)
#define BS_BYTES (32 * BPIT * 2)
#define GEMM_SMEM (3 * (AS_BYTES + BS_BYTES))

template <typename OutT>
__device__ __forceinline__ void gemm_f16_body(const __half* __restrict__ A,
                                              const __half* __restrict__ W,
                                              const float* __restrict__ bias,
                                              OutT* __restrict__ out) {
    extern __shared__ __align__(16) __half gsh[];
    __half* As = gsh;                          // [3][128][APIT]
    __half* Bs = gsh + 3 * 128 * APIT;         // [3][32][BPIT]
    const int tid  = threadIdx.x;
    const int warp = tid >> 5;
    const int lane = tid & 31;
    const int g    = lane >> 2;
    const int tig  = lane & 3;
    const int mf   = lane >> 3;
    const int rr   = lane & 7;
    const int wm   = warp >> 2;
    const int wn   = warp & 3;
    const int m0 = blockIdx.x * 128, n0 = blockIdx.y * 128;

    const uint32_t as_u = (uint32_t)__cvta_generic_to_shared(As);
    const uint32_t bs_u = (uint32_t)__cvta_generic_to_shared(Bs);

    auto issue_tiles = [&](int k0, int buf) {
#pragma unroll
        for (int p = 0; p < 2; p++) {
            int li = p * 256 + tid;        // 128 rows x 4 chunks
            int r  = li >> 2;
            int c  = (li & 3) * 8;
            cp16(as_u + buf * AS_BYTES + (r * APIT + c) * 2,
                 A + (size_t)(m0 + r) * Cc + k0 + c);
        }
#pragma unroll
        for (int p = 0; p < 2; p++) {
            int li = p * 256 + tid;        // 32 rows x 16 chunks
            int r  = li >> 4;
            int c  = (li & 15) * 8;
            cp16(bs_u + buf * BS_BYTES + (r * BPIT + c) * 2,
                 W + (size_t)(k0 + r) * Cc + n0 + c);
        }
    };

    float acc[4][4][4] = {};

    issue_tiles(0, 0);  cp_commit();
    issue_tiles(32, 1); cp_commit();

    for (int kt = 0; kt < 16; kt++) {
        const int cur = kt % 3;
        cp_wait<1>();
        __syncthreads();
        if (kt + 2 < 16) issue_tiles((kt + 2) * 32, (kt + 2) % 3);
        cp_commit();

        const uint32_t abase = as_u + cur * AS_BYTES;
        const uint32_t bbase = bs_u + cur * BS_BYTES;
#pragma unroll
        for (int kc = 0; kc < 2; kc++) {
            uint32_t af[4][4];
#pragma unroll
            for (int mt = 0; mt < 4; mt++) {
                int row = wm * 64 + mt * 16 + rr + (mf & 1) * 8;
                int col = kc * 16 + (mf >> 1) * 8;
                ldsm_x4(af[mt], abase + (row * APIT + col) * 2);
            }
            uint32_t bf[2][4];
#pragma unroll
            for (int p = 0; p < 2; p++) {
                int krow = kc * 16 + (mf & 1) * 8 + rr;
                int ncol = wn * 32 + (2 * p + (mf >> 1)) * 8;
                ldsm_x4_t(bf[p], bbase + (krow * BPIT + ncol) * 2);
            }
#pragma unroll
            for (int mt = 0; mt < 4; mt++)
#pragma unroll
                for (int p = 0; p < 2; p++) {
                    mma_f16(acc[mt][2 * p],     af[mt], bf[p][0], bf[p][1]);
                    mma_f16(acc[mt][2 * p + 1], af[mt], bf[p][2], bf[p][3]);
                }
        }
    }

    // epilogue: add bias, store
#pragma unroll
    for (int mt = 0; mt < 4; mt++) {
        int r0g = m0 + wm * 64 + mt * 16 + g;
        int r1g = r0g + 8;
#pragma unroll
        for (int nt = 0; nt < 4; nt++) {
            int n = n0 + wn * 32 + nt * 8 + 2 * tig;
            float b0 = bias[n], b1 = bias[n + 1];
            float v00 = acc[mt][nt][0] + b0, v01 = acc[mt][nt][1] + b1;
            float v10 = acc[mt][nt][2] + b0, v11 = acc[mt][nt][3] + b1;
            if constexpr (sizeof(OutT) == 2) {
                *(uint32_t*)&out[(size_t)r0g * Cc + n] = h2u(__floats2half2_rn(v00, v01));
                *(uint32_t*)&out[(size_t)r1g * Cc + n] = h2u(__floats2half2_rn(v10, v11));
            } else {
                float2 w0 = {v00, v01};
                float2 w1 = {v10, v11};
                *(float2*)&out[(size_t)r0g * Cc + n] = w0;
                *(float2*)&out[(size_t)r1g * Cc + n] = w1;
            }
        }
    }
}

__global__ __launch_bounds__(256, 2)
void gemm_qkv(const float* __restrict__ bq, const float* __restrict__ bk,
              const float* __restrict__ bv) {
    const __half* W; const float* bi; __half* out;
    if (blockIdx.z == 0)      { W = g_wh[0]; bi = bq; out = g_qh; }
    else if (blockIdx.z == 1) { W = g_wh[1]; bi = bk; out = g_kh; }
    else                      { W = g_wh[2]; bi = bv; out = g_vh; }
    gemm_f16_body<__half>(g_xh, W, bi, out);
}

__global__ __launch_bounds__(256, 2)
void gemm_out(const float* __restrict__ bo, float* __restrict__ out) {
    gemm_f16_body<float>(g_ctxh, g_wh[3], bo, out);
}

// ---------------------------------------------------------------------------
// fp16 tensor-core flash attention: 128-key chunks (2-stage cp.async),
// TWO 64-key subtiles per chunk between ONE sync. Math identical to round 12.
// ---------------------------------------------------------------------------
#define QP 72
#define CHUNK_BYTES (128 * QP * 2)     // one 128-key K or V chunk
// smem: Q(128*QP) + 2*K-chunk + 2*V-chunk (halves) + kneg (2048 f32) = 100352
#define ATTN_SMEM ((128 * QP + 4 * 128 * QP) * 2 + Tt * 4)

__global__ __launch_bounds__(256, 2)
void attn_kernel(const int* __restrict__ mask, const int* __restrict__ cdrs) {
    extern __shared__ __align__(16) __half sh[];
    __half* qs = sh;                        // [128][QP]
    __half* ks = sh + 128 * QP;             // [2][128][QP]
    __half* vs = ks + 2 * 128 * QP;         // [2][128][QP]
    float*  kneg = (float*)(vs + 2 * 128 * QP);   // [2048]

    const int q0   = blockIdx.x * 128;
    const int h    = blockIdx.y;
    const int b    = blockIdx.z;
    const int tid  = threadIdx.x;
    const int warp = tid >> 5;
    const int lane = tid & 31;
    const int g    = lane >> 2;
    const int tig  = lane & 3;
    const int mf   = lane >> 3;
    const int rr   = lane & 7;

    const bool iscdr = (h < CDRH) && (g_allm[b] == 0);

    const uint32_t qs_u = (uint32_t)__cvta_generic_to_shared(qs);
    const uint32_t ks_u = (uint32_t)__cvta_generic_to_shared(ks);
    const uint32_t vs_u = (uint32_t)__cvta_generic_to_shared(vs);

    const __half* kall = g_kh + (size_t)b * Tt * Cc + h * Dd;
    const __half* vall = g_vh + (size_t)b * Tt * Cc + h * Dd;

    // load one 128-key chunk of K and V
    auto issue_kv = [&](int ch, int buf) {
        const __half* kbase = kall + (size_t)ch * 128 * Cc;
        const __half* vbase = vall + (size_t)ch * 128 * Cc;
#pragma unroll
        for (int p = 0; p < 4; p++) {
            int li = p * 256 + tid;       // 128 rows x 8 chunks
            int r  = li >> 3;
            int c  = (li & 7) * 8;
            cp16(ks_u + buf * CHUNK_BYTES + (r * QP + c) * 2,
                 kbase + (size_t)r * Cc + c);
        }
#pragma unroll
        for (int p = 0; p < 4; p++) {
            int li = p * 256 + tid;
            int r  = li >> 3;
            int c  = (li & 7) * 8;
            cp16(vs_u + buf * CHUNK_BYTES + (r * QP + c) * 2,
                 vbase + (size_t)r * Cc + c);
        }
    };

    // ---- prologue: Q + chunk 0; mask bias for all keys ----
    const __half* qbase = g_qh + (size_t)(b * Tt + q0) * Cc + h * Dd;
#pragma unroll
    for (int p = 0; p < 4; p++) {
        int li = p * 256 + tid;
        int r  = li >> 3;
        int c  = (li & 7) * 8;
        cp16(qs_u + (r * QP + c) * 2, qbase + (size_t)r * Cc + c);
    }
    cp_commit();
    issue_kv(0, 0); cp_commit();

#pragma unroll
    for (int p = 0; p < Tt / 256; p++) {
        int kg = p * 256 + tid;
        bool bad = (mask[b * Tt + kg] == 0) ||
                   (iscdr && (cdrs[b * Tt + kg] == 0));
        kneg[kg] = bad ? NEG_INF : 0.f;
    }

    cp_wait<1>();      // Q complete (chunk 0 may be in flight)
    __syncthreads();   // Q + kneg visible

    // ---- hoist Q A-fragments ----
    uint32_t qa[4][4];
#pragma unroll
    for (int kc = 0; kc < 4; kc++) {
        int row = warp * 16 + rr + (mf & 1) * 8;
        int col = kc * 16 + (mf >> 1) * 8;
        ldsm_x4(qa[kc], qs_u + (row * QP + col) * 2);
    }

    float m_run[2] = {M_INIT, M_INIT};
    float l_run[2] = {0.f, 0.f};
    float o[8][4] = {};

    const int NCH = Tt / 128;   // 16 chunks
    for (int ch = 0; ch < NCH; ch++) {
        const int buf = ch & 1;
        cp_wait<0>();      // chunk ch complete
        __syncthreads();   // visibility; prev iteration's buffer drained
        if (ch + 1 < NCH) issue_kv(ch + 1, buf ^ 1);
        cp_commit();

        // two 64-key subtiles, no barrier between (read-only smem)
#pragma unroll
        for (int hf = 0; hf < 2; hf++) {
            const uint32_t kb = ks_u + buf * CHUNK_BYTES + hf * 64 * QP * 2;
            const uint32_t vb = vs_u + buf * CHUNK_BYTES + hf * 64 * QP * 2;
            const float* kn = kneg + ch * 128 + hf * 64;

            // ---- S = Q K^T ----
            float s[8][4] = {};
#pragma unroll
            for (int kc = 0; kc < 4; kc++) {
#pragma unroll
                for (int p = 0; p < 4; p++) {
                    int key = (2 * p + (mf >> 1)) * 8 + rr;
                    int d   = kc * 16 + (mf & 1) * 8;
                    uint32_t bk[4];
                    ldsm_x4(bk, kb + (key * QP + d) * 2);
                    mma_f16(s[2 * p],     qa[kc], bk[0], bk[1]);
                    mma_f16(s[2 * p + 1], qa[kc], bk[2], bk[3]);
                }
            }

            // ---- scale (log2 domain) + key-mask bias ----
#pragma unroll
            for (int nt = 0; nt < 8; nt++) {
                float k0b = kn[nt * 8 + 2 * tig];
                float k1b = kn[nt * 8 + 2 * tig + 1];
                s[nt][0] = s[nt][0] * SCALE2 + k0b;
                s[nt][1] = s[nt][1] * SCALE2 + k1b;
                s[nt][2] = s[nt][2] * SCALE2 + k0b;
                s[nt][3] = s[nt][3] * SCALE2 + k1b;
            }

            // ---- row max (quad reduce) ----
            float mt0 = NEG_INF, mt1 = NEG_INF;
#pragma unroll
            for (int nt = 0; nt < 8; nt++) {
                mt0 = fmaxf(mt0, fmaxf(s[nt][0], s[nt][1]));
                mt1 = fmaxf(mt1, fmaxf(s[nt][2], s[nt][3]));
            }
#pragma unroll
            for (int off = 1; off < 4; off <<= 1) {
                mt0 = fmaxf(mt0, __shfl_xor_sync(0xffffffffu, mt0, off));
                mt1 = fmaxf(mt1, __shfl_xor_sync(0xffffffffu, mt1, off));
            }
            float mn0 = fmaxf(m_run[0], mt0);
            float mn1 = fmaxf(m_run[1], mt1);
            float alpha0 = ex2(m_run[0] - mn0);
            float alpha1 = ex2(m_run[1] - mn1);
            m_run[0] = mn0;
            m_run[1] = mn1;

#pragma unroll
            for (int nt = 0; nt < 8; nt++) {
                o[nt][0] *= alpha0; o[nt][1] *= alpha0;
                o[nt][2] *= alpha1; o[nt][3] *= alpha1;
            }

            // ---- P = exp2(s - m) half2; row sums via ones-MMA; O += P@V ----
            float sc[4] = {0.f, 0.f, 0.f, 0.f};
#pragma unroll
            for (int kc = 0; kc < 4; kc++) {
                const int e = 2 * kc, od = 2 * kc + 1;
                uint32_t pa[4];
                pa[0] = ex2h2(h2u(__floats2half2_rn(s[e][0] - mn0,  s[e][1] - mn0)));
                pa[1] = ex2h2(h2u(__floats2half2_rn(s[e][2] - mn1,  s[e][3] - mn1)));
                pa[2] = ex2h2(h2u(__floats2half2_rn(s[od][0] - mn0, s[od][1] - mn0)));
                pa[3] = ex2h2(h2u(__floats2half2_rn(s[od][2] - mn1, s[od][3] - mn1)));

                mma_f16(sc, pa, ONES_H2, ONES_H2);

#pragma unroll
                for (int p = 0; p < 4; p++) {
                    int key = kc * 16 + (mf & 1) * 8 + rr;
                    int d   = (2 * p + (mf >> 1)) * 8;
                    uint32_t bv[4];
                    ldsm_x4_t(bv, vb + (key * QP + d) * 2);
                    mma_f16(o[2 * p],     pa, bv[0], bv[1]);
                    mma_f16(o[2 * p + 1], pa, bv[2], bv[3]);
                }
            }
            l_run[0] = l_run[0] * alpha0 + sc[0];
            l_run[1] = l_run[1] * alpha1 + sc[2];
        }
    }

    // ---- epilogue: normalize, write ctx (half) ----
    const int r0 = warp * 16 + g;
    const int r1 = r0 + 8;
    float inv0 = 1.f / l_run[0];
    float inv1 = 1.f / l_run[1];
    __half* ob0 = g_ctxh + (size_t)(b * Tt + q0 + r0) * Cc + h * Dd;
    __half* ob1 = g_ctxh + (size_t)(b * Tt + q0 + r1) * Cc + h * Dd;
#pragma unroll
    for (int nt = 0; nt < 8; nt++) {
        *(uint32_t*)&ob0[nt * 8 + 2 * tig] =
            h2u(__floats2half2_rn(o[nt][0] * inv0, o[nt][1] * inv0));
        *(uint32_t*)&ob1[nt * 8 + 2 * tig] =
            h2u(__floats2half2_rn(o[nt][2] * inv1, o[nt][3] * inv1));
    }
}

// ---------------------------------------------------------------------------
// Launch
// ---------------------------------------------------------------------------
extern "C" void kernel_launch(void* const* d_in, const int* in_sizes, int n_in,
                              void* d_out, int out_size) {
    const float* x    = (const float*)d_in[0];
    const int*   mask = (const int*)d_in[1];
    const int*   cdrs = (const int*)d_in[2];
    const float* Wq   = (const float*)d_in[3];
    const float* bq   = (const float*)d_in[4];
    const float* Wk   = (const float*)d_in[5];
    const float* bk   = (const float*)d_in[6];
    const float* Wv   = (const float*)d_in[7];
    const float* bv   = (const float*)d_in[8];
    const float* Wo   = (const float*)d_in[9];
    const float* bo   = (const float*)d_in[10];
    float* out = (float*)d_out;

    dim3 gprep((Bb * Tt * Cc / 4 + 255) / 256, 6);
    prep_kernel<<<gprep, 256>>>(x, Wq, Wk, Wv, Wo, cdrs);

    cudaFuncSetAttribute(gemm_qkv, cudaFuncAttributeMaxDynamicSharedMemorySize,
                         GEMM_SMEM);
    cudaFuncSetAttribute(gemm_out, cudaFuncAttributeMaxDynamicSharedMemorySize,
                         GEMM_SMEM);

    dim3 gqkv(Bb * Tt / 128, Cc / 128, 3);
    gemm_qkv<<<gqkv, 256, GEMM_SMEM>>>(bq, bk, bv);

    cudaFuncSetAttribute(attn_kernel, cudaFuncAttributeMaxDynamicSharedMemorySize,
                         ATTN_SMEM);
    dim3 gatt(Tt / 128, Hh, Bb);
    attn_kernel<<<gatt, 256, ATTN_SMEM>>>(mask, cdrs);

    dim3 gout(Bb * Tt / 128, Cc / 128, 1);
    gemm_out<<<gout, 256, GEMM_SMEM>>>(bo, out);
}

// round 16
// speedup vs baseline: 1.3749x; 1.3749x over previous
#include <cuda_runtime.h>
#include <cuda_fp16.h>
#include <cstdint>

// Problem constants
#define Bb   4
#define Tt   2048
#define Cc   512
#define Hh   8
#define Dd   64
#define CDRH 2

#define NEG_INF  __int_as_float(0xff800000)
#define M_INIT   -1.0e30f
#define SCALE2 0.18033688011112042f   // 0.125 * log2(e)
#define ONES_H2 0x3C003C00u           // half2(1.0, 1.0)

// Scratch (allocation-free: module-static device globals)
__device__ __half g_xh[Bb * Tt * Cc];
__device__ __half g_wh[4][Cc * Cc];    // Wq, Wk, Wv, Wo in half
__device__ __half g_qh[Bb * Tt * Cc];
__device__ __half g_kh[Bb * Tt * Cc];
__device__ __half g_vh[Bb * Tt * Cc];
__device__ __half g_ctxh[Bb * Tt * Cc];
__device__ int    g_allm[Bb];
__device__ int    g_idx[2][Bb * Tt];   // compacted key indices per class
__device__ int    g_nkey[2][Bb];       // valid-key counts per class

// ---------------------------------------------------------------------------
// helpers
// ---------------------------------------------------------------------------
__device__ __forceinline__ void mma_f16(float c[4], const uint32_t a[4],
                                        uint32_t b0, uint32_t b1) {
    asm volatile(
        "mma.sync.aligned.m16n8k16.row.col.f32.f16.f16.f32 "
        "{%0,%1,%2,%3}, {%4,%5,%6,%7}, {%8,%9}, {%0,%1,%2,%3};"
        : "+f"(c[0]), "+f"(c[1]), "+f"(c[2]), "+f"(c[3])
        : "r"(a[0]), "r"(a[1]), "r"(a[2]), "r"(a[3]), "r"(b0), "r"(b1));
}

__device__ __forceinline__ void ldsm_x4(uint32_t r[4], uint32_t addr) {
    asm volatile("ldmatrix.sync.aligned.m8n8.x4.shared.b16 {%0,%1,%2,%3}, [%4];"
                 : "=r"(r[0]), "=r"(r[1]), "=r"(r[2]), "=r"(r[3]) : "r"(addr));
}

__device__ __forceinline__ void ldsm_x4_t(uint32_t r[4], uint32_t addr) {
    asm volatile("ldmatrix.sync.aligned.m8n8.x4.trans.shared.b16 {%0,%1,%2,%3}, [%4];"
                 : "=r"(r[0]), "=r"(r[1]), "=r"(r[2]), "=r"(r[3]) : "r"(addr));
}

__device__ __forceinline__ uint32_t h2u(__half2 h) {
    return *reinterpret_cast<uint32_t*>(&h);
}

__device__ __forceinline__ float ex2(float x) {
    float y;
    asm("ex2.approx.f32 %0, %1;" : "=f"(y) : "f"(x));
    return y;
}

__device__ __forceinline__ uint32_t ex2h2(uint32_t x) {
    uint32_t y;
    asm("ex2.approx.f16x2 %0, %1;" : "=r"(y) : "r"(x));
    return y;
}

__device__ __forceinline__ void cp16(uint32_t dst, const void* src) {
    asm volatile("cp.async.cg.shared.global [%0], [%1], 16;" :: "r"(dst), "l"(src));
}
__device__ __forceinline__ void cp_commit() {
    asm volatile("cp.async.commit_group;");
}
template <int N>
__device__ __forceinline__ void cp_wait() {
    asm volatile("cp.async.wait_group %0;" :: "n"(N));
}

// ---------------------------------------------------------------------------
// Fused prep: fp32->half for x + 4 weights (grid.y 0..4), allm flag (y==5)
// ---------------------------------------------------------------------------
__global__ void prep_kernel(const float* __restrict__ x,
                            const float* __restrict__ Wq,
                            const float* __restrict__ Wk,
                            const float* __restrict__ Wv,
                            const float* __restrict__ Wo,
                            const int* __restrict__ cdrs) {
    const int y = blockIdx.y;
    if (y == 5) {
        int b = blockIdx.x;
        if (b >= Bb) return;
        __shared__ int any;
        if (threadIdx.x == 0) any = 0;
        __syncthreads();
        int local = 0;
        for (int t = threadIdx.x; t < Tt; t += blockDim.x)
            local |= (cdrs[b * Tt + t] != 0);
        if (local) any = 1;
        __syncthreads();
        if (threadIdx.x == 0) g_allm[b] = (any == 0) ? 1 : 0;
        return;
    }
    const float* src; __half* dst; int n4;
    switch (y) {
        case 0: src = x;  dst = g_xh;    n4 = Bb * Tt * Cc / 4; break;
        case 1: src = Wq; dst = g_wh[0]; n4 = Cc * Cc / 4; break;
        case 2: src = Wk; dst = g_wh[1]; n4 = Cc * Cc / 4; break;
        case 3: src = Wv; dst = g_wh[2]; n4 = Cc * Cc / 4; break;
        default: src = Wo; dst = g_wh[3]; n4 = Cc * Cc / 4; break;
    }
    int i = blockIdx.x * blockDim.x + threadIdx.x;
    if (i < n4) {
        float4 v = ((const float4*)src)[i];
        uint2 w;
        w.x = h2u(__floats2half2_rn(v.x, v.y));
        w.y = h2u(__floats2half2_rn(v.z, v.w));
        ((uint2*)dst)[i] = w;
    }
}

// ---------------------------------------------------------------------------
// Key compaction: deterministic prefix-scan per (batch, class).
// class 0: keys with mask==1 (regular heads)
// class 1: keys with mask==1 && (cdrs==1 || allm)  (CDR heads)
// ---------------------------------------------------------------------------
__global__ void compact_kernel(const int* __restrict__ mask,
                               const int* __restrict__ cdrs) {
    const int b   = blockIdx.x;
    const int cls = blockIdx.y;
    const int tid = threadIdx.x;
    const bool am = (g_allm[b] != 0);

    __shared__ int cnt[256];

    int local[8];
    int lc = 0;
#pragma unroll
    for (int i = 0; i < 8; i++) {
        int t = tid * 8 + i;
        bool v = (mask[b * Tt + t] != 0);
        if (cls == 1) v = v && (am || (cdrs[b * Tt + t] != 0));
        if (v) local[lc++] = t;
    }
    cnt[tid] = lc;
    __syncthreads();

    // Hillis-Steele inclusive scan over 256 counts
    for (int off = 1; off < 256; off <<= 1) {
        int v = cnt[tid];
        int u = (tid >= off) ? cnt[tid - off] : 0;
        __syncthreads();
        cnt[tid] = v + u;
        __syncthreads();
    }

    int start = cnt[tid] - lc;
    int* dst = g_idx[cls] + b * Tt;
    for (int i = 0; i < lc; i++) dst[start + i] = local[i];
    if (tid == 255) g_nkey[cls][b] = cnt[255];
}

// ---------------------------------------------------------------------------
// fp16 tensor-core GEMM (round-12 shape), BK=32, 3-stage cp.async.
// ---------------------------------------------------------------------------
#define APIT 40    // As pitch in halves (80 B)
#define BPIT 136   // Bs pitch in halves (272 B)
#define AS_BYTES (128 * APIT * 2)
#define BS_BYTES (32 * BPIT * 2)
#define GEMM_SMEM (3 * (AS_BYTES + BS_BYTES))

template <typename OutT>
__device__ __forceinline__ void gemm_f16_body(const __half* __restrict__ A,
                                              const __half* __restrict__ W,
                                              const float* __restrict__ bias,
                                              OutT* __restrict__ out) {
    extern __shared__ __align__(16) __half gsh[];
    __half* As = gsh;                          // [3][128][APIT]
    __half* Bs = gsh + 3 * 128 * APIT;         // [3][32][BPIT]
    const int tid  = threadIdx.x;
    const int warp = tid >> 5;
    const int lane = tid & 31;
    const int g    = lane >> 2;
    const int tig  = lane & 3;
    const int mf   = lane >> 3;
    const int rr   = lane & 7;
    const int wm   = warp >> 2;
    const int wn   = warp & 3;
    const int m0 = blockIdx.x * 128, n0 = blockIdx.y * 128;

    const uint32_t as_u = (uint32_t)__cvta_generic_to_shared(As);
    const uint32_t bs_u = (uint32_t)__cvta_generic_to_shared(Bs);

    auto issue_tiles = [&](int k0, int buf) {
#pragma unroll
        for (int p = 0; p < 2; p++) {
            int li = p * 256 + tid;
            int r  = li >> 2;
            int c  = (li & 3) * 8;
            cp16(as_u + buf * AS_BYTES + (r * APIT + c) * 2,
                 A + (size_t)(m0 + r) * Cc + k0 + c);
        }
#pragma unroll
        for (int p = 0; p < 2; p++) {
            int li = p * 256 + tid;
            int r  = li >> 4;
            int c  = (li & 15) * 8;
            cp16(bs_u + buf * BS_BYTES + (r * BPIT + c) * 2,
                 W + (size_t)(k0 + r) * Cc + n0 + c);
        }
    };

    float acc[4][4][4] = {};

    issue_tiles(0, 0);  cp_commit();
    issue_tiles(32, 1); cp_commit();

    for (int kt = 0; kt < 16; kt++) {
        const int cur = kt % 3;
        cp_wait<1>();
        __syncthreads();
        if (kt + 2 < 16) issue_tiles((kt + 2) * 32, (kt + 2) % 3);
        cp_commit();

        const uint32_t abase = as_u + cur * AS_BYTES;
        const uint32_t bbase = bs_u + cur * BS_BYTES;
#pragma unroll
        for (int kc = 0; kc < 2; kc++) {
            uint32_t af[4][4];
#pragma unroll
            for (int mt = 0; mt < 4; mt++) {
                int row = wm * 64 + mt * 16 + rr + (mf & 1) * 8;
                int col = kc * 16 + (mf >> 1) * 8;
                ldsm_x4(af[mt], abase + (row * APIT + col) * 2);
            }
            uint32_t bf[2][4];
#pragma unroll
            for (int p = 0; p < 2; p++) {
                int krow = kc * 16 + (mf & 1) * 8 + rr;
                int ncol = wn * 32 + (2 * p + (mf >> 1)) * 8;
                ldsm_x4_t(bf[p], bbase + (krow * BPIT + ncol) * 2);
            }
#pragma unroll
            for (int mt = 0; mt < 4; mt++)
#pragma unroll
                for (int p = 0; p < 2; p++) {
                    mma_f16(acc[mt][2 * p],     af[mt], bf[p][0], bf[p][1]);
                    mma_f16(acc[mt][2 * p + 1], af[mt], bf[p][2], bf[p][3]);
                }
        }
    }

#pragma unroll
    for (int mt = 0; mt < 4; mt++) {
        int r0g = m0 + wm * 64 + mt * 16 + g;
        int r1g = r0g + 8;
#pragma unroll
        for (int nt = 0; nt < 4; nt++) {
            int n = n0 + wn * 32 + nt * 8 + 2 * tig;
            float b0 = bias[n], b1 = bias[n + 1];
            float v00 = acc[mt][nt][0] + b0, v01 = acc[mt][nt][1] + b1;
            float v10 = acc[mt][nt][2] + b0, v11 = acc[mt][nt][3] + b1;
            if constexpr (sizeof(OutT) == 2) {
                *(uint32_t*)&out[(size_t)r0g * Cc + n] = h2u(__floats2half2_rn(v00, v01));
                *(uint32_t*)&out[(size_t)r1g * Cc + n] = h2u(__floats2half2_rn(v10, v11));
            } else {
                float2 w0 = {v00, v01};
                float2 w1 = {v10, v11};
                *(float2*)&out[(size_t)r0g * Cc + n] = w0;
                *(float2*)&out[(size_t)r1g * Cc + n] = w1;
            }
        }
    }
}

__global__ __launch_bounds__(256, 2)
void gemm_qkv(const float* __restrict__ bq, const float* __restrict__ bk,
              const float* __restrict__ bv) {
    const __half* W; const float* bi; __half* out;
    if (blockIdx.z == 0)      { W = g_wh[0]; bi = bq; out = g_qh; }
    else if (blockIdx.z == 1) { W = g_wh[1]; bi = bk; out = g_kh; }
    else                      { W = g_wh[2]; bi = bv; out = g_vh; }
    gemm_f16_body<__half>(g_xh, W, bi, out);
}

__global__ __launch_bounds__(256, 2)
void gemm_out(const float* __restrict__ bo, float* __restrict__ out) {
    gemm_f16_body<float>(g_ctxh, g_wh[3], bo, out);
}

// ---------------------------------------------------------------------------
// fp16 flash attention over COMPACTED keys: per (head-class, batch) index
// list; dynamic tile count ceil(n/64); padding handled by ALU -inf bias.
// 3-stage cp.async, 2 CTAs/SM, half2-ex2 softmax, row sums via ones-MMA.
// ---------------------------------------------------------------------------
#define QP 72
#define KS_BYTES (64 * QP * 2)
#define ATTN_SMEM ((128 * QP + 6 * 64 * QP) * 2)   // 73728

__global__ __launch_bounds__(256, 2)
void attn_kernel(void) {
    extern __shared__ __align__(16) __half sh[];
    __half* qs = sh;                       // [128][QP]
    __half* ks = sh + 128 * QP;            // [3][64][QP]
    __half* vs = ks + 3 * 64 * QP;         // [3][64][QP]

    const int q0   = blockIdx.x * 128;
    const int h    = blockIdx.y;
    const int b    = blockIdx.z;
    const int tid  = threadIdx.x;
    const int warp = tid >> 5;
    const int lane = tid & 31;
    const int g    = lane >> 2;
    const int tig  = lane & 3;
    const int mf   = lane >> 3;
    const int rr   = lane & 7;

    const int cls = (h < CDRH && g_allm[b] == 0) ? 1 : 0;
    const int n   = g_nkey[cls][b];
    const int* __restrict__ idxp = g_idx[cls] + b * Tt;
    const int ntiles = (n + 63) >> 6;

    const uint32_t qs_u = (uint32_t)__cvta_generic_to_shared(qs);
    const uint32_t ks_u = (uint32_t)__cvta_generic_to_shared(ks);
    const uint32_t vs_u = (uint32_t)__cvta_generic_to_shared(vs);

    const __half* kall = g_kh + (size_t)b * Tt * Cc + h * Dd;
    const __half* vall = g_vh + (size_t)b * Tt * Cc + h * Dd;

    auto issue_kv = [&](int kt, int buf) {
#pragma unroll
        for (int p = 0; p < 2; p++) {
            int li = p * 256 + tid;       // 64 rows x 8 chunks
            int r  = li >> 3;
            int c  = (li & 7) * 8;
            int j  = kt * 64 + r;
            int t  = (j < n) ? __ldg(idxp + j) : 0;
            cp16(ks_u + buf * KS_BYTES + (r * QP + c) * 2,
                 kall + (size_t)t * Cc + c);
        }
#pragma unroll
        for (int p = 0; p < 2; p++) {
            int li = p * 256 + tid;
            int r  = li >> 3;
            int c  = (li & 7) * 8;
            int j  = kt * 64 + r;
            int t  = (j < n) ? __ldg(idxp + j) : 0;
            cp16(vs_u + buf * KS_BYTES + (r * QP + c) * 2,
                 vall + (size_t)t * Cc + c);
        }
    };

    // ---- prologue: Q + first 2 key tiles ----
    const __half* qbase = g_qh + (size_t)(b * Tt + q0) * Cc + h * Dd;
#pragma unroll
    for (int p = 0; p < 4; p++) {
        int li = p * 256 + tid;
        int r  = li >> 3;
        int c  = (li & 7) * 8;
        cp16(qs_u + (r * QP + c) * 2, qbase + (size_t)r * Cc + c);
    }
    cp_commit();
    issue_kv(0, 0); cp_commit();
    if (ntiles > 1) issue_kv(1, 1);
    cp_commit();

    cp_wait<2>();      // Q complete
    __syncthreads();

    // ---- hoist Q A-fragments ----
    uint32_t qa[4][4];
#pragma unroll
    for (int kc = 0; kc < 4; kc++) {
        int row = warp * 16 + rr + (mf & 1) * 8;
        int col = kc * 16 + (mf >> 1) * 8;
        ldsm_x4(qa[kc], qs_u + (row * QP + col) * 2);
    }

    float m_run[2] = {M_INIT, M_INIT};
    float l_run[2] = {0.f, 0.f};
    float o[8][4] = {};

    for (int kt = 0; kt < ntiles; kt++) {
        const int cur = kt % 3;
        cp_wait<1>();
        __syncthreads();
        if (kt + 2 < ntiles) issue_kv(kt + 2, (kt + 2) % 3);
        cp_commit();

        const uint32_t kb = ks_u + cur * KS_BYTES;
        const uint32_t vb = vs_u + cur * KS_BYTES;
        const int jbase = kt * 64;

        // ---- S = Q K^T ----
        float s[8][4] = {};
#pragma unroll
        for (int kc = 0; kc < 4; kc++) {
#pragma unroll
            for (int p = 0; p < 4; p++) {
                int key = (2 * p + (mf >> 1)) * 8 + rr;
                int d   = kc * 16 + (mf & 1) * 8;
                uint32_t bk[4];
                ldsm_x4(bk, kb + (key * QP + d) * 2);
                mma_f16(s[2 * p],     qa[kc], bk[0], bk[1]);
                mma_f16(s[2 * p + 1], qa[kc], bk[2], bk[3]);
            }
        }

        // ---- scale (log2 domain) + padding bias (ALU) ----
#pragma unroll
        for (int nt = 0; nt < 8; nt++) {
            int j0 = jbase + nt * 8 + 2 * tig;
            float k0b = (j0     < n) ? 0.f : NEG_INF;
            float k1b = (j0 + 1 < n) ? 0.f : NEG_INF;
            s[nt][0] = s[nt][0] * SCALE2 + k0b;
            s[nt][1] = s[nt][1] * SCALE2 + k1b;
            s[nt][2] = s[nt][2] * SCALE2 + k0b;
            s[nt][3] = s[nt][3] * SCALE2 + k1b;
        }

        // ---- row max (quad reduce) ----
        float mt0 = NEG_INF, mt1 = NEG_INF;
#pragma unroll
        for (int nt = 0; nt < 8; nt++) {
            mt0 = fmaxf(mt0, fmaxf(s[nt][0], s[nt][1]));
            mt1 = fmaxf(mt1, fmaxf(s[nt][2], s[nt][3]));
        }
#pragma unroll
        for (int off = 1; off < 4; off <<= 1) {
            mt0 = fmaxf(mt0, __shfl_xor_sync(0xffffffffu, mt0, off));
            mt1 = fmaxf(mt1, __shfl_xor_sync(0xffffffffu, mt1, off));
        }
        float mn0 = fmaxf(m_run[0], mt0);
        float mn1 = fmaxf(m_run[1], mt1);
        float alpha0 = ex2(m_run[0] - mn0);
        float alpha1 = ex2(m_run[1] - mn1);
        m_run[0] = mn0;
        m_run[1] = mn1;

#pragma unroll
        for (int nt = 0; nt < 8; nt++) {
            o[nt][0] *= alpha0; o[nt][1] *= alpha0;
            o[nt][2] *= alpha1; o[nt][3] *= alpha1;
        }

        // ---- P = exp2(s - m) half2; row sums via ones-MMA; O += P@V ----
        float sc[4] = {0.f, 0.f, 0.f, 0.f};
#pragma unroll
        for (int kc = 0; kc < 4; kc++) {
            const int e = 2 * kc, od = 2 * kc + 1;
            uint32_t pa[4];
            pa[0] = ex2h2(h2u(__floats2half2_rn(s[e][0] - mn0,  s[e][1] - mn0)));
            pa[1] = ex2h2(h2u(__floats2half2_rn(s[e][2] - mn1,  s[e][3] - mn1)));
            pa[2] = ex2h2(h2u(__floats2half2_rn(s[od][0] - mn0, s[od][1] - mn0)));
            pa[3] = ex2h2(h2u(__floats2half2_rn(s[od][2] - mn1, s[od][3] - mn1)));

            mma_f16(sc, pa, ONES_H2, ONES_H2);

#pragma unroll
            for (int p = 0; p < 4; p++) {
                int key = kc * 16 + (mf & 1) * 8 + rr;
                int d   = (2 * p + (mf >> 1)) * 8;
                uint32_t bv[4];
                ldsm_x4_t(bv, vb + (key * QP + d) * 2);
                mma_f16(o[2 * p],     pa, bv[0], bv[1]);
                mma_f16(o[2 * p + 1], pa, bv[2], bv[3]);
            }
        }
        l_run[0] = l_run[0] * alpha0 + sc[0];
        l_run[1] = l_run[1] * alpha1 + sc[2];
    }

    // ---- epilogue: normalize, write ctx (half) ----
    const int r0 = warp * 16 + g;
    const int r1 = r0 + 8;
    float inv0 = 1.f / l_run[0];
    float inv1 = 1.f / l_run[1];
    __half* ob0 = g_ctxh + (size_t)(b * Tt + q0 + r0) * Cc + h * Dd;
    __half* ob1 = g_ctxh + (size_t)(b * Tt + q0 + r1) * Cc + h * Dd;
#pragma unroll
    for (int nt = 0; nt < 8; nt++) {
        *(uint32_t*)&ob0[nt * 8 + 2 * tig] =
            h2u(__floats2half2_rn(o[nt][0] * inv0, o[nt][1] * inv0));
        *(uint32_t*)&ob1[nt * 8 + 2 * tig] =
            h2u(__floats2half2_rn(o[nt][2] * inv1, o[nt][3] * inv1));
    }
}

// ---------------------------------------------------------------------------
// Launch
// ---------------------------------------------------------------------------
extern "C" void kernel_launch(void* const* d_in, const int* in_sizes, int n_in,
                              void* d_out, int out_size) {
    const float* x    = (const float*)d_in[0];
    const int*   mask = (const int*)d_in[1];
    const int*   cdrs = (const int*)d_in[2];
    const float* Wq   = (const float*)d_in[3];
    const float* bq   = (const float*)d_in[4];
    const float* Wk   = (const float*)d_in[5];
    const float* bk   = (const float*)d_in[6];
    const float* Wv   = (const float*)d_in[7];
    const float* bv   = (const float*)d_in[8];
    const float* Wo   = (const float*)d_in[9];
    const float* bo   = (const float*)d_in[10];
    float* out = (float*)d_out;

    // prep: x/W conversions + allm flag
    dim3 gprep((Bb * Tt * Cc / 4 + 255) / 256, 6);
    prep_kernel<<<gprep, 256>>>(x, Wq, Wk, Wv, Wo, cdrs);

    // key compaction (needs g_allm from prep; same stream = ordered)
    dim3 gcomp(Bb, 2);
    compact_kernel<<<gcomp, 256>>>(mask, cdrs);

    cudaFuncSetAttribute(gemm_qkv, cudaFuncAttributeMaxDynamicSharedMemorySize,
                         GEMM_SMEM);
    cudaFuncSetAttribute(gemm_out, cudaFuncAttributeMaxDynamicSharedMemorySize,
                         GEMM_SMEM);

    dim3 gqkv(Bb * Tt / 128, Cc / 128, 3);
    gemm_qkv<<<gqkv, 256, GEMM_SMEM>>>(bq, bk, bv);

    cudaFuncSetAttribute(attn_kernel, cudaFuncAttributeMaxDynamicSharedMemorySize,
                         ATTN_SMEM);
    dim3 gatt(Tt / 128, Hh, Bb);
    attn_kernel<<<gatt, 256, ATTN_SMEM>>>();

    dim3 gout(Bb * Tt / 128, Cc / 128, 1);
    gemm_out<<<gout, 256, GEMM_SMEM>>>(bo, out);
}

// round 17
// speedup vs baseline: 1.5004x; 1.0913x over previous
#include <cuda_runtime.h>
#include <cuda_fp16.h>
#include <cstdint>

// Problem constants
#define Bb   4
#define Tt   2048
#define Cc   512
#define Hh   8
#define Dd   64
#define CDRH 2

#define NEG_INF  __int_as_float(0xff800000)
#define M_INIT   -1.0e30f
#define SCALE2 0.18033688011112042f   // 0.125 * log2(e)
#define ONES_H2 0x3C003C00u           // half2(1.0, 1.0)

// Scratch (allocation-free: module-static device globals)
__device__ __half g_xh[Bb * Tt * Cc];
__device__ __half g_wh[4][Cc * Cc];    // Wq, Wk, Wv, Wo in half
__device__ __half g_qh[Bb * Tt * Cc];
__device__ __half g_kh[Bb * Tt * Cc];  // COMPACTED K (valid keys first)
__device__ __half g_vh[Bb * Tt * Cc];  // COMPACTED V
__device__ __half g_ctxh[Bb * Tt * Cc];
__device__ int    g_allm[Bb];
__device__ int    g_gidx[Bb * Tt];     // gather: compacted pos -> token id
__device__ int    g_ridx[Bb * Tt];     // cls1: j -> rank in compacted array
__device__ int    g_nkey[2][Bb];       // valid-key counts per class

// ---------------------------------------------------------------------------
// helpers
// ---------------------------------------------------------------------------
__device__ __forceinline__ void mma_f16(float c[4], const uint32_t a[4],
                                        uint32_t b0, uint32_t b1) {
    asm volatile(
        "mma.sync.aligned.m16n8k16.row.col.f32.f16.f16.f32 "
        "{%0,%1,%2,%3}, {%4,%5,%6,%7}, {%8,%9}, {%0,%1,%2,%3};"
        : "+f"(c[0]), "+f"(c[1]), "+f"(c[2]), "+f"(c[3])
        : "r"(a[0]), "r"(a[1]), "r"(a[2]), "r"(a[3]), "r"(b0), "r"(b1));
}

__device__ __forceinline__ void ldsm_x4(uint32_t r[4], uint32_t addr) {
    asm volatile("ldmatrix.sync.aligned.m8n8.x4.shared.b16 {%0,%1,%2,%3}, [%4];"
                 : "=r"(r[0]), "=r"(r[1]), "=r"(r[2]), "=r"(r[3]) : "r"(addr));
}

__device__ __forceinline__ void ldsm_x4_t(uint32_t r[4], uint32_t addr) {
    asm volatile("ldmatrix.sync.aligned.m8n8.x4.trans.shared.b16 {%0,%1,%2,%3}, [%4];"
                 : "=r"(r[0]), "=r"(r[1]), "=r"(r[2]), "=r"(r[3]) : "r"(addr));
}

__device__ __forceinline__ uint32_t h2u(__half2 h) {
    return *reinterpret_cast<uint32_t*>(&h);
}

__device__ __forceinline__ float ex2(float x) {
    float y;
    asm("ex2.approx.f32 %0, %1;" : "=f"(y) : "f"(x));
    return y;
}

__device__ __forceinline__ uint32_t ex2h2(uint32_t x) {
    uint32_t y;
    asm("ex2.approx.f16x2 %0, %1;" : "=r"(y) : "r"(x));
    return y;
}

__device__ __forceinline__ void cp16(uint32_t dst, const void* src) {
    asm volatile("cp.async.cg.shared.global [%0], [%1], 16;" :: "r"(dst), "l"(src));
}
__device__ __forceinline__ void cp_commit() {
    asm volatile("cp.async.commit_group;");
}
template <int N>
__device__ __forceinline__ void cp_wait() {
    asm volatile("cp.async.wait_group %0;" :: "n"(N));
}

// ---------------------------------------------------------------------------
// Fused prep: fp32->half for x + 4 weights (grid.y 0..4), allm flag (y==5)
// ---------------------------------------------------------------------------
__global__ void prep_kernel(const float* __restrict__ x,
                            const float* __restrict__ Wq,
                            const float* __restrict__ Wk,
                            const float* __restrict__ Wv,
                            const float* __restrict__ Wo,
                            const int* __restrict__ cdrs) {
    const int y = blockIdx.y;
    if (y == 5) {
        int b = blockIdx.x;
        if (b >= Bb) return;
        __shared__ int any;
        if (threadIdx.x == 0) any = 0;
        __syncthreads();
        int local = 0;
        for (int t = threadIdx.x; t < Tt; t += blockDim.x)
            local |= (cdrs[b * Tt + t] != 0);
        if (local) any = 1;
        __syncthreads();
        if (threadIdx.x == 0) g_allm[b] = (any == 0) ? 1 : 0;
        return;
    }
    const float* src; __half* dst; int n4;
    switch (y) {
        case 0: src = x;  dst = g_xh;    n4 = Bb * Tt * Cc / 4; break;
        case 1: src = Wq; dst = g_wh[0]; n4 = Cc * Cc / 4; break;
        case 2: src = Wk; dst = g_wh[1]; n4 = Cc * Cc / 4; break;
        case 3: src = Wv; dst = g_wh[2]; n4 = Cc * Cc / 4; break;
        default: src = Wo; dst = g_wh[3]; n4 = Cc * Cc / 4; break;
    }
    int i = blockIdx.x * blockDim.x + threadIdx.x;
    if (i < n4) {
        float4 v = ((const float4*)src)[i];
        uint2 w;
        w.x = h2u(__floats2half2_rn(v.x, v.y));
        w.y = h2u(__floats2half2_rn(v.z, v.w));
        ((uint2*)dst)[i] = w;
    }
}

// ---------------------------------------------------------------------------
// Compaction: one block per batch. Produces
//   g_gidx: compacted position -> token id   (mask==1, for K/V gather GEMM)
//   g_ridx: cls1 j -> rank within compacted  (mask && (cdr || allm))
//   g_nkey[0][b]=n0, g_nkey[1][b]=n1
// ---------------------------------------------------------------------------
__global__ void compact_kernel(const int* __restrict__ mask,
                               const int* __restrict__ cdrs) {
    const int b   = blockIdx.x;
    const int tid = threadIdx.x;
    const bool am = (g_allm[b] != 0);

    __shared__ int cnt[256];

    bool mv[8], c1[8];
    int mcnt = 0, ccnt = 0;
#pragma unroll
    for (int i = 0; i < 8; i++) {
        int t = tid * 8 + i;
        mv[i] = (mask[b * Tt + t] != 0);
        c1[i] = mv[i] && (am || (cdrs[b * Tt + t] != 0));
        mcnt += mv[i];
        ccnt += c1[i];
    }

    // scan class-0 counts
    cnt[tid] = mcnt;
    __syncthreads();
    for (int off = 1; off < 256; off <<= 1) {
        int v = cnt[tid];
        int u = (tid >= off) ? cnt[tid - off] : 0;
        __syncthreads();
        cnt[tid] = v + u;
        __syncthreads();
    }
    int base0 = cnt[tid] - mcnt;
    int n0 = cnt[255];
    __syncthreads();

    int rank[8];   // rank-in-compacted for each valid t
    {
        int k = base0;
#pragma unroll
        for (int i = 0; i < 8; i++) {
            rank[i] = k;
            if (mv[i]) {
                g_gidx[b * Tt + k] = tid * 8 + i;
                k++;
            }
        }
    }

    // scan class-1 counts
    cnt[tid] = ccnt;
    __syncthreads();
    for (int off = 1; off < 256; off <<= 1) {
        int v = cnt[tid];
        int u = (tid >= off) ? cnt[tid - off] : 0;
        __syncthreads();
        cnt[tid] = v + u;
        __syncthreads();
    }
    int base1 = cnt[tid] - ccnt;
    {
        int k = base1;
#pragma unroll
        for (int i = 0; i < 8; i++) {
            if (c1[i]) g_ridx[b * Tt + k++] = rank[i];
        }
    }
    if (tid == 255) {
        g_nkey[0][b] = n0;
        g_nkey[1][b] = cnt[255];
    }
}

// ---------------------------------------------------------------------------
// fp16 tensor-core GEMM core (round-12 shape), BK=32, 3-stage cp.async.
// Gather==true: A rows selected through g_gidx (K/V compacted GEMM).
// ---------------------------------------------------------------------------
#define APIT 40    // As pitch in halves (80 B)
#define BPIT 136   // Bs pitch in halves (272 B)
#define AS_BYTES (128 * APIT * 2)
#define BS_BYTES (32 * BPIT * 2)
#define GEMM_SMEM (3 * (AS_BYTES + BS_BYTES))

template <typename OutT, bool Gather>
__device__ __forceinline__ void gemm_f16_core(const __half* __restrict__ A,
                                              const __half* __restrict__ W,
                                              const float* __restrict__ bias,
                                              OutT* __restrict__ out,
                                              int m0, int n0,
                                              const int* __restrict__ gidx,
                                              int nrow) {
    extern __shared__ __align__(16) __half gsh[];
    __half* As = gsh;                          // [3][128][APIT]
    __half* Bs = gsh + 3 * 128 * APIT;         // [3][32][BPIT]
    const int tid  = threadIdx.x;
    const int warp = tid >> 5;
    const int lane = tid & 31;
    const int g    = lane >> 2;
    const int tig  = lane & 3;
    const int mf   = lane >> 3;
    const int rr   = lane & 7;
    const int wm   = warp >> 2;
    const int wn   = warp & 3;

    const uint32_t as_u = (uint32_t)__cvta_generic_to_shared(As);
    const uint32_t bs_u = (uint32_t)__cvta_generic_to_shared(Bs);

    auto issue_tiles = [&](int k0, int buf) {
#pragma unroll
        for (int p = 0; p < 2; p++) {
            int li = p * 256 + tid;
            int r  = li >> 2;
            int c  = (li & 3) * 8;
            size_t arow;
            if constexpr (Gather) {
                int m = m0 + r;
                if (m >= nrow) m = nrow - 1;
                arow = (size_t)__ldg(gidx + m);
            } else {
                arow = (size_t)(m0 + r);
            }
            cp16(as_u + buf * AS_BYTES + (r * APIT + c) * 2,
                 A + arow * Cc + k0 + c);
        }
#pragma unroll
        for (int p = 0; p < 2; p++) {
            int li = p * 256 + tid;
            int r  = li >> 4;
            int c  = (li & 15) * 8;
            cp16(bs_u + buf * BS_BYTES + (r * BPIT + c) * 2,
                 W + (size_t)(k0 + r) * Cc + n0 + c);
        }
    };

    float acc[4][4][4] = {};

    issue_tiles(0, 0);  cp_commit();
    issue_tiles(32, 1); cp_commit();

    for (int kt = 0; kt < 16; kt++) {
        const int cur = kt % 3;
        cp_wait<1>();
        __syncthreads();
        if (kt + 2 < 16) issue_tiles((kt + 2) * 32, (kt + 2) % 3);
        cp_commit();

        const uint32_t abase = as_u + cur * AS_BYTES;
        const uint32_t bbase = bs_u + cur * BS_BYTES;
#pragma unroll
        for (int kc = 0; kc < 2; kc++) {
            uint32_t af[4][4];
#pragma unroll
            for (int mt = 0; mt < 4; mt++) {
                int row = wm * 64 + mt * 16 + rr + (mf & 1) * 8;
                int col = kc * 16 + (mf >> 1) * 8;
                ldsm_x4(af[mt], abase + (row * APIT + col) * 2);
            }
            uint32_t bf[2][4];
#pragma unroll
            for (int p = 0; p < 2; p++) {
                int krow = kc * 16 + (mf & 1) * 8 + rr;
                int ncol = wn * 32 + (2 * p + (mf >> 1)) * 8;
                ldsm_x4_t(bf[p], bbase + (krow * BPIT + ncol) * 2);
            }
#pragma unroll
            for (int mt = 0; mt < 4; mt++)
#pragma unroll
                for (int p = 0; p < 2; p++) {
                    mma_f16(acc[mt][2 * p],     af[mt], bf[p][0], bf[p][1]);
                    mma_f16(acc[mt][2 * p + 1], af[mt], bf[p][2], bf[p][3]);
                }
        }
    }

#pragma unroll
    for (int mt = 0; mt < 4; mt++) {
        int r0g = m0 + wm * 64 + mt * 16 + g;
        int r1g = r0g + 8;
#pragma unroll
        for (int nt = 0; nt < 4; nt++) {
            int n = n0 + wn * 32 + nt * 8 + 2 * tig;
            float b0 = bias[n], b1 = bias[n + 1];
            float v00 = acc[mt][nt][0] + b0, v01 = acc[mt][nt][1] + b1;
            float v10 = acc[mt][nt][2] + b0, v11 = acc[mt][nt][3] + b1;
            if constexpr (sizeof(OutT) == 2) {
                *(uint32_t*)&out[(size_t)r0g * Cc + n] = h2u(__floats2half2_rn(v00, v01));
                *(uint32_t*)&out[(size_t)r1g * Cc + n] = h2u(__floats2half2_rn(v10, v11));
            } else {
                float2 w0 = {v00, v01};
                float2 w1 = {v10, v11};
                *(float2*)&out[(size_t)r0g * Cc + n] = w0;
                *(float2*)&out[(size_t)r1g * Cc + n] = w1;
            }
        }
    }
}

// Q projection: full M = B*T
__global__ __launch_bounds__(256, 2)
void gemm_q(const float* __restrict__ bq) {
    gemm_f16_core<__half, false>(g_xh, g_wh[0], bq, g_qh,
                                 blockIdx.x * 128, blockIdx.y * 128, nullptr, 0);
}

// K/V projection over compacted valid keys only.
// grid.z encodes (kv, batch): z = kv*Bb + b. Early-exit tiles beyond n0[b].
__global__ __launch_bounds__(256, 2)
void gemm_kv(const float* __restrict__ bk, const float* __restrict__ bv) {
    const int kv = blockIdx.z / Bb;
    const int b  = blockIdx.z % Bb;
    const int n0 = g_nkey[0][b];
    const int m0 = blockIdx.x * 128;
    if (m0 >= n0) return;
    const __half* W  = kv ? g_wh[2] : g_wh[1];
    const float*  bi = kv ? bv : bk;
    __half* out = (kv ? g_vh : g_kh) + (size_t)b * Tt * Cc;
    gemm_f16_core<__half, true>(g_xh + (size_t)b * Tt * Cc, W, bi, out,
                                m0, blockIdx.y * 128,
                                g_gidx + b * Tt, n0);
}

__global__ __launch_bounds__(256, 2)
void gemm_out(const float* __restrict__ bo, float* __restrict__ out) {
    gemm_f16_core<float, false>(g_ctxh, g_wh[3], bo, out,
                                blockIdx.x * 128, blockIdx.y * 128, nullptr, 0);
}

// ---------------------------------------------------------------------------
// fp16 flash attention over COMPACTED K/V. Class-0 heads read contiguously;
// class-1 heads read through the rank index. Padding via ALU -inf bias.
// ---------------------------------------------------------------------------
#define QP 72
#define KS_BYTES (64 * QP * 2)
#define ATTN_SMEM ((128 * QP + 6 * 64 * QP) * 2)   // 73728

__global__ __launch_bounds__(256, 2)
void attn_kernel(void) {
    extern __shared__ __align__(16) __half sh[];
    __half* qs = sh;                       // [128][QP]
    __half* ks = sh + 128 * QP;            // [3][64][QP]
    __half* vs = ks + 3 * 64 * QP;         // [3][64][QP]

    const int q0   = blockIdx.x * 128;
    const int h    = blockIdx.y;
    const int b    = blockIdx.z;
    const int tid  = threadIdx.x;
    const int warp = tid >> 5;
    const int lane = tid & 31;
    const int g    = lane >> 2;
    const int tig  = lane & 3;
    const int mf   = lane >> 3;
    const int rr   = lane & 7;

    const int cls = (h < CDRH && g_allm[b] == 0) ? 1 : 0;
    const int n   = g_nkey[cls][b];
    const int* __restrict__ ridx = g_ridx + b * Tt;
    const int ntiles = (n + 63) >> 6;

    const uint32_t qs_u = (uint32_t)__cvta_generic_to_shared(qs);
    const uint32_t ks_u = (uint32_t)__cvta_generic_to_shared(ks);
    const uint32_t vs_u = (uint32_t)__cvta_generic_to_shared(vs);

    const __half* kall = g_kh + (size_t)b * Tt * Cc + h * Dd;
    const __half* vall = g_vh + (size_t)b * Tt * Cc + h * Dd;

    auto issue_kv = [&](int kt, int buf) {
#pragma unroll
        for (int p = 0; p < 2; p++) {
            int li = p * 256 + tid;       // 64 rows x 8 chunks
            int r  = li >> 3;
            int c  = (li & 7) * 8;
            int j  = kt * 64 + r;
            int t;
            if (cls == 0) t = (j < n) ? j : (n - 1);
            else          t = (j < n) ? __ldg(ridx + j) : 0;
            cp16(ks_u + buf * KS_BYTES + (r * QP + c) * 2,
                 kall + (size_t)t * Cc + c);
        }
#pragma unroll
        for (int p = 0; p < 2; p++) {
            int li = p * 256 + tid;
            int r  = li >> 3;
            int c  = (li & 7) * 8;
            int j  = kt * 64 + r;
            int t;
            if (cls == 0) t = (j < n) ? j : (n - 1);
            else          t = (j < n) ? __ldg(ridx + j) : 0;
            cp16(vs_u + buf * KS_BYTES + (r * QP + c) * 2,
                 vall + (size_t)t * Cc + c);
        }
    };

    // ---- prologue: Q + first 2 key tiles ----
    const __half* qbase = g_qh + (size_t)(b * Tt + q0) * Cc + h * Dd;
#pragma unroll
    for (int p = 0; p < 4; p++) {
        int li = p * 256 + tid;
        int r  = li >> 3;
        int c  = (li & 7) * 8;
        cp16(qs_u + (r * QP + c) * 2, qbase + (size_t)r * Cc + c);
    }
    cp_commit();
    issue_kv(0, 0); cp_commit();
    if (ntiles > 1) issue_kv(1, 1);
    cp_commit();

    cp_wait<2>();      // Q complete
    __syncthreads();

    // ---- hoist Q A-fragments ----
    uint32_t qa[4][4];
#pragma unroll
    for (int kc = 0; kc < 4; kc++) {
        int row = warp * 16 + rr + (mf & 1) * 8;
        int col = kc * 16 + (mf >> 1) * 8;
        ldsm_x4(qa[kc], qs_u + (row * QP + col) * 2);
    }

    float m_run[2] = {M_INIT, M_INIT};
    float l_run[2] = {0.f, 0.f};
    float o[8][4] = {};

    for (int kt = 0; kt < ntiles; kt++) {
        const int cur = kt % 3;
        cp_wait<1>();
        __syncthreads();
        if (kt + 2 < ntiles) issue_kv(kt + 2, (kt + 2) % 3);
        cp_commit();

        const uint32_t kb = ks_u + cur * KS_BYTES;
        const uint32_t vb = vs_u + cur * KS_BYTES;
        const int jbase = kt * 64;

        // ---- S = Q K^T ----
        float s[8][4] = {};
#pragma unroll
        for (int kc = 0; kc < 4; kc++) {
#pragma unroll
            for (int p = 0; p < 4; p++) {
                int key = (2 * p + (mf >> 1)) * 8 + rr;
                int d   = kc * 16 + (mf & 1) * 8;
                uint32_t bk[4];
                ldsm_x4(bk, kb + (key * QP + d) * 2);
                mma_f16(s[2 * p],     qa[kc], bk[0], bk[1]);
                mma_f16(s[2 * p + 1], qa[kc], bk[2], bk[3]);
            }
        }

        // ---- scale (log2 domain) + padding bias (ALU) ----
#pragma unroll
        for (int nt = 0; nt < 8; nt++) {
            int j0 = jbase + nt * 8 + 2 * tig;
            float k0b = (j0     < n) ? 0.f : NEG_INF;
            float k1b = (j0 + 1 < n) ? 0.f : NEG_INF;
            s[nt][0] = s[nt][0] * SCALE2 + k0b;
            s[nt][1] = s[nt][1] * SCALE2 + k1b;
            s[nt][2] = s[nt][2] * SCALE2 + k0b;
            s[nt][3] = s[nt][3] * SCALE2 + k1b;
        }

        // ---- row max (quad reduce) ----
        float mt0 = NEG_INF, mt1 = NEG_INF;
#pragma unroll
        for (int nt = 0; nt < 8; nt++) {
            mt0 = fmaxf(mt0, fmaxf(s[nt][0], s[nt][1]));
            mt1 = fmaxf(mt1, fmaxf(s[nt][2], s[nt][3]));
        }
#pragma unroll
        for (int off = 1; off < 4; off <<= 1) {
            mt0 = fmaxf(mt0, __shfl_xor_sync(0xffffffffu, mt0, off));
            mt1 = fmaxf(mt1, __shfl_xor_sync(0xffffffffu, mt1, off));
        }
        float mn0 = fmaxf(m_run[0], mt0);
        float mn1 = fmaxf(m_run[1], mt1);
        float alpha0 = ex2(m_run[0] - mn0);
        float alpha1 = ex2(m_run[1] - mn1);
        m_run[0] = mn0;
        m_run[1] = mn1;

#pragma unroll
        for (int nt = 0; nt < 8; nt++) {
            o[nt][0] *= alpha0; o[nt][1] *= alpha0;
            o[nt][2] *= alpha1; o[nt][3] *= alpha1;
        }

        // ---- P = exp2(s - m) half2; row sums via ones-MMA; O += P@V ----
        float sc[4] = {0.f, 0.f, 0.f, 0.f};
#pragma unroll
        for (int kc = 0; kc < 4; kc++) {
            const int e = 2 * kc, od = 2 * kc + 1;
            uint32_t pa[4];
            pa[0] = ex2h2(h2u(__floats2half2_rn(s[e][0] - mn0,  s[e][1] - mn0)));
            pa[1] = ex2h2(h2u(__floats2half2_rn(s[e][2] - mn1,  s[e][3] - mn1)));
            pa[2] = ex2h2(h2u(__floats2half2_rn(s[od][0] - mn0, s[od][1] - mn0)));
            pa[3] = ex2h2(h2u(__floats2half2_rn(s[od][2] - mn1, s[od][3] - mn1)));

            mma_f16(sc, pa, ONES_H2, ONES_H2);

#pragma unroll
            for (int p = 0; p < 4; p++) {
                int key = kc * 16 + (mf & 1) * 8 + rr;
                int d   = (2 * p + (mf >> 1)) * 8;
                uint32_t bv[4];
                ldsm_x4_t(bv, vb + (key * QP + d) * 2);
                mma_f16(o[2 * p],     pa, bv[0], bv[1]);
                mma_f16(o[2 * p + 1], pa, bv[2], bv[3]);
            }
        }
        l_run[0] = l_run[0] * alpha0 + sc[0];
        l_run[1] = l_run[1] * alpha1 + sc[2];
    }

    // ---- epilogue: normalize, write ctx (half) ----
    const int r0 = warp * 16 + g;
    const int r1 = r0 + 8;
    float inv0 = 1.f / l_run[0];
    float inv1 = 1.f / l_run[1];
    __half* ob0 = g_ctxh + (size_t)(b * Tt + q0 + r0) * Cc + h * Dd;
    __half* ob1 = g_ctxh + (size_t)(b * Tt + q0 + r1) * Cc + h * Dd;
#pragma unroll
    for (int nt = 0; nt < 8; nt++) {
        *(uint32_t*)&ob0[nt * 8 + 2 * tig] =
            h2u(__floats2half2_rn(o[nt][0] * inv0, o[nt][1] * inv0));
        *(uint32_t*)&ob1[nt * 8 + 2 * tig] =
            h2u(__floats2half2_rn(o[nt][2] * inv1, o[nt][3] * inv1));
    }
}

// ---------------------------------------------------------------------------
// Launch
// ---------------------------------------------------------------------------
extern "C" void kernel_launch(void* const* d_in, const int* in_sizes, int n_in,
                              void* d_out, int out_size) {
    const float* x    = (const float*)d_in[0];
    const int*   mask = (const int*)d_in[1];
    const int*   cdrs = (const int*)d_in[2];
    const float* Wq   = (const float*)d_in[3];
    const float* bq   = (const float*)d_in[4];
    const float* Wk   = (const float*)d_in[5];
    const float* bk   = (const float*)d_in[6];
    const float* Wv   = (const float*)d_in[7];
    const float* bv   = (const float*)d_in[8];
    const float* Wo   = (const float*)d_in[9];
    const float* bo   = (const float*)d_in[10];
    float* out = (float*)d_out;

    // prep: x/W conversions + allm flag
    dim3 gprep((Bb * Tt * Cc / 4 + 255) / 256, 6);
    prep_kernel<<<gprep, 256>>>(x, Wq, Wk, Wv, Wo, cdrs);

    // key compaction (one block per batch; needs g_allm; same stream = ordered)
    compact_kernel<<<Bb, 256>>>(mask, cdrs);

    cudaFuncSetAttribute(gemm_q,   cudaFuncAttributeMaxDynamicSharedMemorySize, GEMM_SMEM);
    cudaFuncSetAttribute(gemm_kv,  cudaFuncAttributeMaxDynamicSharedMemorySize, GEMM_SMEM);
    cudaFuncSetAttribute(gemm_out, cudaFuncAttributeMaxDynamicSharedMemorySize, GEMM_SMEM);

    // Q: full M; K/V: compacted M per batch (early-exit tiles)
    dim3 gq(Bb * Tt / 128, Cc / 128);
    gemm_q<<<gq, 256, GEMM_SMEM>>>(bq);
    dim3 gkv(Tt / 128, Cc / 128, 2 * Bb);
    gemm_kv<<<gkv, 256, GEMM_SMEM>>>(bk, bv);

    cudaFuncSetAttribute(attn_kernel, cudaFuncAttributeMaxDynamicSharedMemorySize,
                         ATTN_SMEM);
    dim3 gatt(Tt / 128, Hh, Bb);
    attn_kernel<<<gatt, 256, ATTN_SMEM>>>();

    dim3 gout(Bb * Tt / 128, Cc / 128, 1);
    gemm_out<<<gout, 256, GEMM_SMEM>>>(bo, out);
}